// round 6
// baseline (speedup 1.0000x reference)
#include <cuda_runtime.h>

typedef unsigned long long ull;

#define NEDGES 3200000
#define NNODES 100000

// Scratch (static device allocation is allowed; no cudaMalloc anywhere)
static __device__ __align__(256) float g_g1[NNODES * 16];  // x@W1^T + (b0+b1+b2)
static __device__ __align__(256) float g_g2[NNODES * 16];  // x@W2^T
static __device__ float g_accum[32];                       // sum[16], sumsq[16]
static __device__ float g_scale[16];
static __device__ float g_shift[16];

// ---- f32x2 packed helpers (ptxas will not auto-fuse; must come from PTX) ----
__device__ __forceinline__ ull pack2(float lo, float hi) {
    ull r; asm("mov.b64 %0, {%1, %2};" : "=l"(r) : "f"(lo), "f"(hi)); return r;
}
__device__ __forceinline__ void unpack2(ull v, float& lo, float& hi) {
    asm("mov.b64 {%0, %1}, %2;" : "=f"(lo), "=f"(hi) : "l"(v));
}
__device__ __forceinline__ ull fma2(ull a, ull b, ull c) {
    ull d; asm("fma.rn.f32x2 %0, %1, %2, %3;" : "=l"(d) : "l"(a), "l"(b), "l"(c)); return d;
}
__device__ __forceinline__ ull add2(ull a, ull b) {
    ull d; asm("add.rn.f32x2 %0, %1, %2;" : "=l"(d) : "l"(a), "l"(b)); return d;
}

// ============================================================================
// Kernel 1: per-node precompute g1 = x@W1^T + (b0+b1+b2), g2 = x@W2^T.
// Also zeroes the stat accumulators (runs before edge_stats in stream order).
// ============================================================================
__global__ void node_prep(const float* __restrict__ x,
                          const float* __restrict__ W1,
                          const float* __restrict__ W2,
                          const float* __restrict__ b0,
                          const float* __restrict__ b1,
                          const float* __restrict__ b2) {
    __shared__ float W1t[256], W2t[256], bt[16];
    int tid = threadIdx.x;
    {
        int j = tid >> 4, k = tid & 15;          // W[j][k] at flat idx tid
        W1t[k * 16 + j] = W1[tid];               // transpose to [k][j]
        W2t[k * 16 + j] = W2[tid];
    }
    if (tid < 16) bt[tid] = b0[tid] + b1[tid] + b2[tid];
    __syncthreads();

    int n = blockIdx.x * blockDim.x + tid;
    if (n < NNODES) {
        const float4* xv = (const float4*)x + n * 4;
        float4 x0 = xv[0], x1 = xv[1], x2 = xv[2], x3 = xv[3];
        float xr[16] = {x0.x, x0.y, x0.z, x0.w, x1.x, x1.y, x1.z, x1.w,
                        x2.x, x2.y, x2.z, x2.w, x3.x, x3.y, x3.z, x3.w};
        float a1[16], a2[16];
        #pragma unroll
        for (int j = 0; j < 16; j++) { a1[j] = bt[j]; a2[j] = 0.f; }
        #pragma unroll
        for (int k = 0; k < 16; k++) {
            float xk = xr[k];
            #pragma unroll
            for (int j = 0; j < 16; j++) {
                a1[j] = fmaf(xk, W1t[k * 16 + j], a1[j]);
                a2[j] = fmaf(xk, W2t[k * 16 + j], a2[j]);
            }
        }
        float4* o1 = (float4*)g_g1 + n * 4;
        float4* o2 = (float4*)g_g2 + n * 4;
        o1[0] = make_float4(a1[0], a1[1], a1[2], a1[3]);
        o1[1] = make_float4(a1[4], a1[5], a1[6], a1[7]);
        o1[2] = make_float4(a1[8], a1[9], a1[10], a1[11]);
        o1[3] = make_float4(a1[12], a1[13], a1[14], a1[15]);
        o2[0] = make_float4(a2[0], a2[1], a2[2], a2[3]);
        o2[1] = make_float4(a2[4], a2[5], a2[6], a2[7]);
        o2[2] = make_float4(a2[8], a2[9], a2[10], a2[11]);
        o2[3] = make_float4(a2[12], a2[13], a2[14], a2[15]);
    }
    if (blockIdx.x == 0 && tid < 32) g_accum[tid] = 0.f;
}

// Shared helper: load W0 pairs into shared. Wp[k*8+p] = (W0[2p][k], W0[2p+1][k])
__device__ __forceinline__ void load_w0_pairs(ull* Wp, const float* __restrict__ W0, int tid) {
    if (tid < 128) {
        int k = tid >> 3, p = tid & 7;
        Wp[k * 8 + p] = pack2(W0[(2 * p) * 16 + k], W0[(2 * p + 1) * 16 + k]);
    }
}

// Per-edge e computation as 8 packed f32x2 accumulators.
__device__ __forceinline__ void compute_e(ull* P, int e, int s, int d,
                                          const float4* __restrict__ eav,
                                          const ull* Wp) {
    const ulonglong2* g1v = (const ulonglong2*)g_g1;
    const ulonglong2* g2v = (const ulonglong2*)g_g2;
    ulonglong2 ga0 = g1v[s * 4 + 0], ga1 = g1v[s * 4 + 1],
               ga2 = g1v[s * 4 + 2], ga3 = g1v[s * 4 + 3];
    ulonglong2 gb0 = g2v[d * 4 + 0], gb1 = g2v[d * 4 + 1],
               gb2 = g2v[d * 4 + 2], gb3 = g2v[d * 4 + 3];
    P[0] = add2(ga0.x, gb0.x); P[1] = add2(ga0.y, gb0.y);
    P[2] = add2(ga1.x, gb1.x); P[3] = add2(ga1.y, gb1.y);
    P[4] = add2(ga2.x, gb2.x); P[5] = add2(ga2.y, gb2.y);
    P[6] = add2(ga3.x, gb3.x); P[7] = add2(ga3.y, gb3.y);
    float4 e0 = eav[e * 4 + 0], e1 = eav[e * 4 + 1],
           e2 = eav[e * 4 + 2], e3 = eav[e * 4 + 3];
    float xr[16] = {e0.x, e0.y, e0.z, e0.w, e1.x, e1.y, e1.z, e1.w,
                    e2.x, e2.y, e2.z, e2.w, e3.x, e3.y, e3.z, e3.w};
    #pragma unroll
    for (int k = 0; k < 16; k++) {
        ull a = pack2(xr[k], xr[k]);
        #pragma unroll
        for (int p = 0; p < 8; p++) P[p] = fma2(a, Wp[k * 8 + p], P[p]);
    }
}

// ============================================================================
// Kernel 2: pass 1 over edges — compute e, accumulate sum / sumsq per feature.
// edge_index is int32 on device (JAX x64 disabled downcasts jnp.int64).
// ============================================================================
__global__ void __launch_bounds__(256) edge_stats(const float* __restrict__ ea,
                                                  const int* __restrict__ ei,
                                                  const float* __restrict__ W0) {
    __shared__ ull Wp[128];
    __shared__ float red[8][32];
    int tid = threadIdx.x;
    load_w0_pairs(Wp, W0, tid);
    __syncthreads();

    ull S[8], Q[8];
    #pragma unroll
    for (int p = 0; p < 8; p++) { S[p] = 0ull; Q[p] = 0ull; }

    const float4* eav = (const float4*)ea;
    int stride = gridDim.x * blockDim.x;
    for (int e = blockIdx.x * blockDim.x + tid; e < NEDGES; e += stride) {
        int s = ei[e];
        int d = ei[NEDGES + e];
        ull P[8];
        compute_e(P, e, s, d, eav, Wp);
        #pragma unroll
        for (int p = 0; p < 8; p++) {
            S[p] = add2(S[p], P[p]);
            Q[p] = fma2(P[p], P[p], Q[p]);
        }
    }

    // warp butterfly reduce 32 scalars, then cross-warp via shared, then atomics
    float v[32];
    #pragma unroll
    for (int p = 0; p < 8; p++) {
        unpack2(S[p], v[2 * p], v[2 * p + 1]);
        unpack2(Q[p], v[16 + 2 * p], v[16 + 2 * p + 1]);
    }
    #pragma unroll
    for (int i = 0; i < 32; i++) {
        #pragma unroll
        for (int o = 16; o > 0; o >>= 1) v[i] += __shfl_xor_sync(0xffffffffu, v[i], o);
    }
    int w = tid >> 5, l = tid & 31;
    if (l == 0) {
        #pragma unroll
        for (int i = 0; i < 32; i++) red[w][i] = v[i];
    }
    __syncthreads();
    if (tid < 32) {
        float acc = 0.f;
        #pragma unroll
        for (int w2 = 0; w2 < 8; w2++) acc += red[w2][tid];
        atomicAdd(&g_accum[tid], acc);
    }
}

// ============================================================================
// Kernel 3: finalize BN affine: scale = gamma*rsqrt(var+eps), shift = beta - mean*scale
// ============================================================================
__global__ void bn_finalize(const float* __restrict__ gamma,
                            const float* __restrict__ beta) {
    int j = threadIdx.x;
    if (j < 16) {
        float inv_n = 1.0f / (float)NEDGES;
        float mean = g_accum[j] * inv_n;
        float var = g_accum[16 + j] * inv_n - mean * mean;
        float sc = gamma[j] * rsqrtf(var + 1e-5f);
        g_scale[j] = sc;
        g_shift[j] = beta[j] - mean * sc;
    }
}

// ============================================================================
// Kernel 4: pass 2 over edges — recompute e, apply BN affine + ReLU + residual.
// ============================================================================
__global__ void __launch_bounds__(256) edge_out(const float* __restrict__ ea,
                                                const int* __restrict__ ei,
                                                const float* __restrict__ W0,
                                                float* __restrict__ out) {
    __shared__ ull Wp[128];
    int tid = threadIdx.x;
    load_w0_pairs(Wp, W0, tid);
    __syncthreads();

    ull scp[8], shp[8];
    #pragma unroll
    for (int p = 0; p < 8; p++) {
        scp[p] = pack2(g_scale[2 * p], g_scale[2 * p + 1]);
        shp[p] = pack2(g_shift[2 * p], g_shift[2 * p + 1]);
    }

    const float4* eav = (const float4*)ea;
    float4* outv = (float4*)out;
    int stride = gridDim.x * blockDim.x;
    for (int e = blockIdx.x * blockDim.x + tid; e < NEDGES; e += stride) {
        int s = ei[e];
        int d = ei[NEDGES + e];
        ull P[8];
        compute_e(P, e, s, d, eav, Wp);
        #pragma unroll
        for (int p = 0; p < 8; p++) P[p] = fma2(P[p], scp[p], shp[p]);

        float4 e0 = eav[e * 4 + 0], e1 = eav[e * 4 + 1],
               e2 = eav[e * 4 + 2], e3 = eav[e * 4 + 3];
        float f[16];
        #pragma unroll
        for (int p = 0; p < 8; p++) unpack2(P[p], f[2 * p], f[2 * p + 1]);
        float4 o0 = make_float4(e0.x + fmaxf(f[0], 0.f),  e0.y + fmaxf(f[1], 0.f),
                                e0.z + fmaxf(f[2], 0.f),  e0.w + fmaxf(f[3], 0.f));
        float4 o1 = make_float4(e1.x + fmaxf(f[4], 0.f),  e1.y + fmaxf(f[5], 0.f),
                                e1.z + fmaxf(f[6], 0.f),  e1.w + fmaxf(f[7], 0.f));
        float4 o2 = make_float4(e2.x + fmaxf(f[8], 0.f),  e2.y + fmaxf(f[9], 0.f),
                                e2.z + fmaxf(f[10], 0.f), e2.w + fmaxf(f[11], 0.f));
        float4 o3 = make_float4(e3.x + fmaxf(f[12], 0.f), e3.y + fmaxf(f[13], 0.f),
                                e3.z + fmaxf(f[14], 0.f), e3.w + fmaxf(f[15], 0.f));
        outv[e * 4 + 0] = o0;
        outv[e * 4 + 1] = o1;
        outv[e * 4 + 2] = o2;
        outv[e * 4 + 3] = o3;
    }
}

extern "C" void kernel_launch(void* const* d_in, const int* in_sizes, int n_in,
                              void* d_out, int out_size) {
    (void)in_sizes; (void)n_in; (void)out_size;
    const float* x     = (const float*)d_in[0];
    const int*   ei    = (const int*)d_in[1];     // int64 in reference, int32 on device (JAX x64 off)
    const float* ea    = (const float*)d_in[2];
    const float* W0    = (const float*)d_in[3];
    const float* b0    = (const float*)d_in[4];
    const float* W1    = (const float*)d_in[5];
    const float* b1    = (const float*)d_in[6];
    const float* W2    = (const float*)d_in[7];
    const float* b2    = (const float*)d_in[8];
    const float* gamma = (const float*)d_in[9];
    const float* beta  = (const float*)d_in[10];
    float* out = (float*)d_out;

    node_prep<<<(NNODES + 255) / 256, 256>>>(x, W1, W2, b0, b1, b2);
    edge_stats<<<1184, 256>>>(ea, ei, W0);
    bn_finalize<<<1, 32>>>(gamma, beta);
    edge_out<<<2368, 256>>>(ea, ei, W0, out);
}

// round 7
// speedup vs baseline: 1.1765x; 1.1765x over previous
#include <cuda_runtime.h>

#define NEDGES 3200000
#define NNODES 100000

// Scratch (static device allocation; no cudaMalloc anywhere)
static __device__ __align__(256) float g_g1[NNODES * 16];  // x@W1^T + (b0+b1+b2)
static __device__ __align__(256) float g_g2[NNODES * 16];  // x@W2^T
static __device__ float g_accum[32];                       // sum[16], sumsq[16]
static __device__ float g_scale[16];
static __device__ float g_shift[16];

// ============================================================================
// Kernel 1: per-node precompute g1 = x@W1^T + (b0+b1+b2), g2 = x@W2^T.
// Also zeroes the stat accumulators (stream-ordered before edge_stats).
// ============================================================================
__global__ void node_prep(const float* __restrict__ x,
                          const float* __restrict__ W1,
                          const float* __restrict__ W2,
                          const float* __restrict__ b0,
                          const float* __restrict__ b1,
                          const float* __restrict__ b2) {
    __shared__ float W1t[256], W2t[256], bt[16];
    int tid = threadIdx.x;
    {
        int j = tid >> 4, k = tid & 15;          // W[j][k] at flat idx tid
        W1t[k * 16 + j] = W1[tid];               // transpose to [k][j]
        W2t[k * 16 + j] = W2[tid];
    }
    if (tid < 16) bt[tid] = b0[tid] + b1[tid] + b2[tid];
    __syncthreads();

    int n = blockIdx.x * blockDim.x + tid;
    if (n < NNODES) {
        const float4* xv = (const float4*)x + n * 4;
        float4 x0 = xv[0], x1 = xv[1], x2 = xv[2], x3 = xv[3];
        float xr[16] = {x0.x, x0.y, x0.z, x0.w, x1.x, x1.y, x1.z, x1.w,
                        x2.x, x2.y, x2.z, x2.w, x3.x, x3.y, x3.z, x3.w};
        float a1[16], a2[16];
        #pragma unroll
        for (int j = 0; j < 16; j++) { a1[j] = bt[j]; a2[j] = 0.f; }
        #pragma unroll
        for (int k = 0; k < 16; k++) {
            float xk = xr[k];
            #pragma unroll
            for (int j = 0; j < 16; j++) {
                a1[j] = fmaf(xk, W1t[k * 16 + j], a1[j]);
                a2[j] = fmaf(xk, W2t[k * 16 + j], a2[j]);
            }
        }
        float4* o1 = (float4*)g_g1 + n * 4;
        float4* o2 = (float4*)g_g2 + n * 4;
        o1[0] = make_float4(a1[0], a1[1], a1[2], a1[3]);
        o1[1] = make_float4(a1[4], a1[5], a1[6], a1[7]);
        o1[2] = make_float4(a1[8], a1[9], a1[10], a1[11]);
        o1[3] = make_float4(a1[12], a1[13], a1[14], a1[15]);
        o2[0] = make_float4(a2[0], a2[1], a2[2], a2[3]);
        o2[1] = make_float4(a2[4], a2[5], a2[6], a2[7]);
        o2[2] = make_float4(a2[8], a2[9], a2[10], a2[11]);
        o2[3] = make_float4(a2[12], a2[13], a2[14], a2[15]);
    }
    if (blockIdx.x == 0 && tid < 32) g_accum[tid] = 0.f;
}

// Load W0 transposed into shared: Wt[k*16+j] = W0[j][k]
__device__ __forceinline__ void load_w0t(float* Wt, const float* __restrict__ W0, int tid) {
    if (tid < 256) {
        int j = tid >> 4, k = tid & 15;
        Wt[k * 16 + j] = W0[j * 16 + k];
    }
}

// Per-edge e computation: acc[16] = ea@W0^T + g1[s] + g2[d]  (bias folded in g1)
// Also returns the raw edge_attr float4s (for the residual in pass 2).
__device__ __forceinline__ void compute_e(float* acc, int e, int s, int d,
                                          const float4* __restrict__ eav,
                                          const float* Wt,
                                          float4& e0, float4& e1, float4& e2, float4& e3) {
    const float4* g1v = (const float4*)g_g1 + s * 4;
    const float4* g2v = (const float4*)g_g2 + d * 4;
    float4 a0 = g1v[0], a1 = g1v[1], a2 = g1v[2], a3 = g1v[3];
    float4 c0 = g2v[0], c1 = g2v[1], c2 = g2v[2], c3 = g2v[3];
    acc[0]  = a0.x + c0.x; acc[1]  = a0.y + c0.y; acc[2]  = a0.z + c0.z; acc[3]  = a0.w + c0.w;
    acc[4]  = a1.x + c1.x; acc[5]  = a1.y + c1.y; acc[6]  = a1.z + c1.z; acc[7]  = a1.w + c1.w;
    acc[8]  = a2.x + c2.x; acc[9]  = a2.y + c2.y; acc[10] = a2.z + c2.z; acc[11] = a2.w + c2.w;
    acc[12] = a3.x + c3.x; acc[13] = a3.y + c3.y; acc[14] = a3.z + c3.z; acc[15] = a3.w + c3.w;

    e0 = eav[e * 4 + 0]; e1 = eav[e * 4 + 1]; e2 = eav[e * 4 + 2]; e3 = eav[e * 4 + 3];
    float xr[16] = {e0.x, e0.y, e0.z, e0.w, e1.x, e1.y, e1.z, e1.w,
                    e2.x, e2.y, e2.z, e2.w, e3.x, e3.y, e3.z, e3.w};
    #pragma unroll
    for (int k = 0; k < 16; k++) {
        float xk = xr[k];
        #pragma unroll
        for (int j = 0; j < 16; j++)
            acc[j] = fmaf(xk, Wt[k * 16 + j], acc[j]);
    }
}

// ============================================================================
// Kernel 2: pass 1 over edges — compute e, accumulate sum / sumsq per feature.
// edge_index is int32 on device (JAX x64 disabled downcasts jnp.int64).
// ============================================================================
__global__ void __launch_bounds__(256) edge_stats(const float* __restrict__ ea,
                                                  const int* __restrict__ ei,
                                                  const float* __restrict__ W0) {
    __shared__ float Wt[256];
    __shared__ float red[8][32];
    int tid = threadIdx.x;
    load_w0t(Wt, W0, tid);
    __syncthreads();

    float S[16], Q[16];
    #pragma unroll
    for (int j = 0; j < 16; j++) { S[j] = 0.f; Q[j] = 0.f; }

    const float4* eav = (const float4*)ea;
    int stride = gridDim.x * blockDim.x;
    for (int e = blockIdx.x * blockDim.x + tid; e < NEDGES; e += stride) {
        int s = ei[e];
        int d = ei[NEDGES + e];
        float acc[16];
        float4 e0, e1, e2, e3;
        compute_e(acc, e, s, d, eav, Wt, e0, e1, e2, e3);
        #pragma unroll
        for (int j = 0; j < 16; j++) {
            S[j] += acc[j];
            Q[j] = fmaf(acc[j], acc[j], Q[j]);
        }
    }

    // warp butterfly reduce 32 scalars, then cross-warp via shared, then atomics
    float v[32];
    #pragma unroll
    for (int j = 0; j < 16; j++) { v[j] = S[j]; v[16 + j] = Q[j]; }
    #pragma unroll
    for (int i = 0; i < 32; i++) {
        #pragma unroll
        for (int o = 16; o > 0; o >>= 1) v[i] += __shfl_xor_sync(0xffffffffu, v[i], o);
    }
    int w = tid >> 5, l = tid & 31;
    if (l == 0) {
        #pragma unroll
        for (int i = 0; i < 32; i++) red[w][i] = v[i];
    }
    __syncthreads();
    if (tid < 32) {
        float acc = 0.f;
        #pragma unroll
        for (int w2 = 0; w2 < 8; w2++) acc += red[w2][tid];
        atomicAdd(&g_accum[tid], acc);
    }
}

// ============================================================================
// Kernel 3: finalize BN affine
// ============================================================================
__global__ void bn_finalize(const float* __restrict__ gamma,
                            const float* __restrict__ beta) {
    int j = threadIdx.x;
    if (j < 16) {
        float inv_n = 1.0f / (float)NEDGES;
        float mean = g_accum[j] * inv_n;
        float var = g_accum[16 + j] * inv_n - mean * mean;
        float sc = gamma[j] * rsqrtf(var + 1e-5f);
        g_scale[j] = sc;
        g_shift[j] = beta[j] - mean * sc;
    }
}

// ============================================================================
// Kernel 4: pass 2 — recompute e, apply BN affine + ReLU + residual.
// Exactly one edge per thread: 3.2M / 256 = 12500 blocks, no bounds check.
// ============================================================================
__global__ void __launch_bounds__(256) edge_out(const float* __restrict__ ea,
                                                const int* __restrict__ ei,
                                                const float* __restrict__ W0,
                                                float* __restrict__ out) {
    __shared__ float Wt[256];
    __shared__ float sc_s[16], sh_s[16];
    int tid = threadIdx.x;
    load_w0t(Wt, W0, tid);
    if (tid < 16) { sc_s[tid] = g_scale[tid]; sh_s[tid] = g_shift[tid]; }
    __syncthreads();

    const float4* eav = (const float4*)ea;
    float4* outv = (float4*)out;
    int e = blockIdx.x * blockDim.x + tid;
    int s = ei[e];
    int d = ei[NEDGES + e];
    float acc[16];
    float4 e0, e1, e2, e3;
    compute_e(acc, e, s, d, eav, Wt, e0, e1, e2, e3);

    float f[16];
    #pragma unroll
    for (int j = 0; j < 16; j++)
        f[j] = fmaxf(fmaf(acc[j], sc_s[j], sh_s[j]), 0.f);

    outv[e * 4 + 0] = make_float4(e0.x + f[0],  e0.y + f[1],  e0.z + f[2],  e0.w + f[3]);
    outv[e * 4 + 1] = make_float4(e1.x + f[4],  e1.y + f[5],  e1.z + f[6],  e1.w + f[7]);
    outv[e * 4 + 2] = make_float4(e2.x + f[8],  e2.y + f[9],  e2.z + f[10], e2.w + f[11]);
    outv[e * 4 + 3] = make_float4(e3.x + f[12], e3.y + f[13], e3.z + f[14], e3.w + f[15]);
}

extern "C" void kernel_launch(void* const* d_in, const int* in_sizes, int n_in,
                              void* d_out, int out_size) {
    (void)in_sizes; (void)n_in; (void)out_size;
    const float* x     = (const float*)d_in[0];
    const int*   ei    = (const int*)d_in[1];     // int32 on device (JAX x64 off)
    const float* ea    = (const float*)d_in[2];
    const float* W0    = (const float*)d_in[3];
    const float* b0    = (const float*)d_in[4];
    const float* W1    = (const float*)d_in[5];
    const float* b1    = (const float*)d_in[6];
    const float* W2    = (const float*)d_in[7];
    const float* b2    = (const float*)d_in[8];
    const float* gamma = (const float*)d_in[9];
    const float* beta  = (const float*)d_in[10];
    float* out = (float*)d_out;

    node_prep<<<(NNODES + 255) / 256, 256>>>(x, W1, W2, b0, b1, b2);
    edge_stats<<<1184, 256>>>(ea, ei, W0);
    bn_finalize<<<1, 32>>>(gamma, beta);
    edge_out<<<NEDGES / 256, 256>>>(ea, ei, W0, out);
}

// round 8
// speedup vs baseline: 1.6056x; 1.3647x over previous
#include <cuda_runtime.h>

#define NEDGES 3200000
#define NNODES 100000

// Scratch (static device allocation; no cudaMalloc anywhere)
static __device__ __align__(256) float g_g1[NNODES * 16];  // x@W1^T + (b0+b1+b2)
static __device__ __align__(256) float g_g2[NNODES * 16];  // x@W2^T
static __device__ float g_accum[32];                       // sum[16], sumsq[16]
static __device__ __align__(64) float g_scale[16];
static __device__ __align__(64) float g_shift[16];

// ============================================================================
// Kernel 1: per-node precompute g1 = x@W1^T + (b0+b1+b2), g2 = x@W2^T.
// Also zeroes the stat accumulators (stream-ordered before edge_stats).
// ============================================================================
__global__ void node_prep(const float* __restrict__ x,
                          const float* __restrict__ W1,
                          const float* __restrict__ W2,
                          const float* __restrict__ b0,
                          const float* __restrict__ b1,
                          const float* __restrict__ b2) {
    __shared__ float W1t[256], W2t[256], bt[16];
    int tid = threadIdx.x;
    {
        int j = tid >> 4, k = tid & 15;          // W[j][k] at flat idx tid
        W1t[k * 16 + j] = W1[tid];               // transpose to [k][j]
        W2t[k * 16 + j] = W2[tid];
    }
    if (tid < 16) bt[tid] = b0[tid] + b1[tid] + b2[tid];
    __syncthreads();

    int n = blockIdx.x * blockDim.x + tid;
    if (n < NNODES) {
        const float4* xv = (const float4*)x + n * 4;
        float4 x0 = xv[0], x1 = xv[1], x2 = xv[2], x3 = xv[3];
        float xr[16] = {x0.x, x0.y, x0.z, x0.w, x1.x, x1.y, x1.z, x1.w,
                        x2.x, x2.y, x2.z, x2.w, x3.x, x3.y, x3.z, x3.w};
        float a1[16], a2[16];
        #pragma unroll
        for (int j = 0; j < 16; j++) { a1[j] = bt[j]; a2[j] = 0.f; }
        #pragma unroll
        for (int k = 0; k < 16; k++) {
            float xk = xr[k];
            #pragma unroll
            for (int j = 0; j < 16; j++) {
                a1[j] = fmaf(xk, W1t[k * 16 + j], a1[j]);
                a2[j] = fmaf(xk, W2t[k * 16 + j], a2[j]);
            }
        }
        float4* o1 = (float4*)g_g1 + n * 4;
        float4* o2 = (float4*)g_g2 + n * 4;
        o1[0] = make_float4(a1[0], a1[1], a1[2], a1[3]);
        o1[1] = make_float4(a1[4], a1[5], a1[6], a1[7]);
        o1[2] = make_float4(a1[8], a1[9], a1[10], a1[11]);
        o1[3] = make_float4(a1[12], a1[13], a1[14], a1[15]);
        o2[0] = make_float4(a2[0], a2[1], a2[2], a2[3]);
        o2[1] = make_float4(a2[4], a2[5], a2[6], a2[7]);
        o2[2] = make_float4(a2[8], a2[9], a2[10], a2[11]);
        o2[3] = make_float4(a2[12], a2[13], a2[14], a2[15]);
    }
    if (blockIdx.x == 0 && tid < 32) g_accum[tid] = 0.f;
}

// Wt[k*16+j] = W0[j][k]; read as float4: Wt4[k*4+q] = W0[4q..4q+3][k]
__device__ __forceinline__ void load_w0t(float* Wt, const float* __restrict__ W0, int tid) {
    if (tid < 256) {
        int j = tid >> 4, k = tid & 15;
        Wt[k * 16 + j] = W0[j * 16 + k];
    }
}

// Quad-cooperative per-edge e computation. Thread q owns features 4q..4q+3.
// acc[i] = e_{4q+i} = (ea@W0^T)_{4q+i} + g1[s]_{4q+i} + g2[d]_{4q+i}
// av = this thread's float4 slice of edge_attr (also the residual slice).
__device__ __forceinline__ void compute_e_quad(float* acc, float4 av, int s, int d,
                                               int q, int lane, const float4* Wt4) {
    const float4* g1v = (const float4*)g_g1;
    const float4* g2v = (const float4*)g_g2;
    float4 ga = g1v[s * 4 + q];
    float4 gb = g2v[d * 4 + q];
    acc[0] = ga.x + gb.x; acc[1] = ga.y + gb.y;
    acc[2] = ga.z + gb.z; acc[3] = ga.w + gb.w;

    float mx0 = av.x, mx1 = av.y, mx2 = av.z, mx3 = av.w;
    int qbase = lane & 28;
    #pragma unroll
    for (int g = 0; g < 4; g++) {
        int src = qbase | g;
        float x0 = __shfl_sync(0xffffffffu, mx0, src);
        float x1 = __shfl_sync(0xffffffffu, mx1, src);
        float x2 = __shfl_sync(0xffffffffu, mx2, src);
        float x3 = __shfl_sync(0xffffffffu, mx3, src);
        // W columns for features 4q..4q+3, rows k=4g..4g+3 (broadcast LDS.128)
        float4 w0 = Wt4[(4 * g + 0) * 4 + q];
        float4 w1 = Wt4[(4 * g + 1) * 4 + q];
        float4 w2 = Wt4[(4 * g + 2) * 4 + q];
        float4 w3 = Wt4[(4 * g + 3) * 4 + q];
        acc[0] = fmaf(x0, w0.x, acc[0]); acc[1] = fmaf(x0, w0.y, acc[1]);
        acc[2] = fmaf(x0, w0.z, acc[2]); acc[3] = fmaf(x0, w0.w, acc[3]);
        acc[0] = fmaf(x1, w1.x, acc[0]); acc[1] = fmaf(x1, w1.y, acc[1]);
        acc[2] = fmaf(x1, w1.z, acc[2]); acc[3] = fmaf(x1, w1.w, acc[3]);
        acc[0] = fmaf(x2, w2.x, acc[0]); acc[1] = fmaf(x2, w2.y, acc[1]);
        acc[2] = fmaf(x2, w2.z, acc[2]); acc[3] = fmaf(x2, w2.w, acc[3]);
        acc[0] = fmaf(x3, w3.x, acc[0]); acc[1] = fmaf(x3, w3.y, acc[1]);
        acc[2] = fmaf(x3, w3.z, acc[2]); acc[3] = fmaf(x3, w3.w, acc[3]);
    }
}

// ============================================================================
// Kernel 2: pass 1 — compute e per edge (quad layout), accumulate sum/sumsq.
// Grid chosen so qstride divides NEDGES exactly (no partial-warp shuffles).
// ============================================================================
__global__ void __launch_bounds__(256) edge_stats(const float* __restrict__ ea,
                                                  const int* __restrict__ ei,
                                                  const float* __restrict__ W0) {
    __shared__ __align__(16) float Wt[256];
    __shared__ float red[8][32];
    int tid = threadIdx.x;
    load_w0t(Wt, W0, tid);
    __syncthreads();
    const float4* Wt4 = (const float4*)Wt;

    int q = tid & 3;
    int lane = tid & 31;
    int qid0 = (blockIdx.x * blockDim.x + tid) >> 2;
    int qstride = (gridDim.x * blockDim.x) >> 2;

    float S[4] = {0.f, 0.f, 0.f, 0.f};
    float Q[4] = {0.f, 0.f, 0.f, 0.f};
    const float4* eav = (const float4*)ea;

    for (int e = qid0; e < NEDGES; e += qstride) {
        int s = ei[e];
        int d = ei[NEDGES + e];
        float4 av = eav[e * 4 + q];   // lane-consecutive: fully coalesced
        float acc[4];
        compute_e_quad(acc, av, s, d, q, lane, Wt4);
        #pragma unroll
        for (int i = 0; i < 4; i++) {
            S[i] += acc[i];
            Q[i] = fmaf(acc[i], acc[i], Q[i]);
        }
    }

    // Reduce across lanes with same q (offsets 4,8,16): lanes 0..3 hold totals
    #pragma unroll
    for (int i = 0; i < 4; i++) {
        #pragma unroll
        for (int o = 4; o < 32; o <<= 1) {
            S[i] += __shfl_xor_sync(0xffffffffu, S[i], o);
            Q[i] += __shfl_xor_sync(0xffffffffu, Q[i], o);
        }
    }
    int w = tid >> 5;
    if (lane < 4) {
        #pragma unroll
        for (int i = 0; i < 4; i++) {
            red[w][lane * 4 + i] = S[i];          // feature j = 4*lane + i
            red[w][16 + lane * 4 + i] = Q[i];
        }
    }
    __syncthreads();
    if (tid < 32) {
        float acc = 0.f;
        #pragma unroll
        for (int w2 = 0; w2 < 8; w2++) acc += red[w2][tid];
        atomicAdd(&g_accum[tid], acc);
    }
}

// ============================================================================
// Kernel 3: finalize BN affine
// ============================================================================
__global__ void bn_finalize(const float* __restrict__ gamma,
                            const float* __restrict__ beta) {
    int j = threadIdx.x;
    if (j < 16) {
        float inv_n = 1.0f / (float)NEDGES;
        float mean = g_accum[j] * inv_n;
        float var = g_accum[16 + j] * inv_n - mean * mean;
        float sc = gamma[j] * rsqrtf(var + 1e-5f);
        g_scale[j] = sc;
        g_shift[j] = beta[j] - mean * sc;
    }
}

// ============================================================================
// Kernel 4: pass 2 — recompute e, BN affine + ReLU + residual (quad layout).
// ============================================================================
__global__ void __launch_bounds__(256) edge_out(const float* __restrict__ ea,
                                                const int* __restrict__ ei,
                                                const float* __restrict__ W0,
                                                float* __restrict__ out) {
    __shared__ __align__(16) float Wt[256];
    int tid = threadIdx.x;
    load_w0t(Wt, W0, tid);
    __syncthreads();
    const float4* Wt4 = (const float4*)Wt;

    int q = tid & 3;
    int lane = tid & 31;
    int qid0 = (blockIdx.x * blockDim.x + tid) >> 2;
    int qstride = (gridDim.x * blockDim.x) >> 2;

    // per-thread BN affine for features 4q..4q+3 (broadcast global loads, once)
    float4 sc = ((const float4*)g_scale)[q];
    float4 sh = ((const float4*)g_shift)[q];

    const float4* eav = (const float4*)ea;
    float4* outv = (float4*)out;

    for (int e = qid0; e < NEDGES; e += qstride) {
        int s = ei[e];
        int d = ei[NEDGES + e];
        float4 av = eav[e * 4 + q];
        float acc[4];
        compute_e_quad(acc, av, s, d, q, lane, Wt4);
        float4 o;
        o.x = av.x + fmaxf(fmaf(acc[0], sc.x, sh.x), 0.f);
        o.y = av.y + fmaxf(fmaf(acc[1], sc.y, sh.y), 0.f);
        o.z = av.z + fmaxf(fmaf(acc[2], sc.z, sh.z), 0.f);
        o.w = av.w + fmaxf(fmaf(acc[3], sc.w, sh.w), 0.f);
        outv[e * 4 + q] = o;                       // lane-consecutive store
    }
}

extern "C" void kernel_launch(void* const* d_in, const int* in_sizes, int n_in,
                              void* d_out, int out_size) {
    (void)in_sizes; (void)n_in; (void)out_size;
    const float* x     = (const float*)d_in[0];
    const int*   ei    = (const int*)d_in[1];     // int32 on device (JAX x64 off)
    const float* ea    = (const float*)d_in[2];
    const float* W0    = (const float*)d_in[3];
    const float* b0    = (const float*)d_in[4];
    const float* W1    = (const float*)d_in[5];
    const float* b1    = (const float*)d_in[6];
    const float* W2    = (const float*)d_in[7];
    const float* b2    = (const float*)d_in[8];
    const float* gamma = (const float*)d_in[9];
    const float* beta  = (const float*)d_in[10];
    float* out = (float*)d_out;

    node_prep<<<(NNODES + 255) / 256, 256>>>(x, W1, W2, b0, b1, b2);
    // qstride = blocks*64 must divide NEDGES=3.2M: 1250*64=80000 (40 iters),
    // 2500*64=160000 (20 iters) — exact, keeps warps converged for shuffles.
    edge_stats<<<1250, 256>>>(ea, ei, W0);
    bn_finalize<<<1, 32>>>(gamma, beta);
    edge_out<<<2500, 256>>>(ea, ei, W0, out);
}

// round 9
// speedup vs baseline: 1.7322x; 1.0789x over previous
#include <cuda_runtime.h>
#include <cuda_fp16.h>

#define NEDGES 3200000
#define NNODES 100000

// Scratch (static device allocation; no cudaMalloc anywhere)
static __device__ __align__(256) float g_g1[NNODES * 16];   // x@W1^T + (b0+b1+b2)
static __device__ __align__(256) float g_g2[NNODES * 16];   // x@W2^T
static __device__ __align__(256) __half g_e[NEDGES * 16];   // fp16 pre-BN e (102.4 MB)
static __device__ float g_accum[32];                        // sum[16], sumsq[16]
static __device__ __align__(64) float g_scale[16];
static __device__ __align__(64) float g_shift[16];

struct __align__(8) h4 { __half2 a, b; };                   // 4 halves = 8 B

// ============================================================================
// Kernel 1: per-node precompute g1 = x@W1^T + (b0+b1+b2), g2 = x@W2^T.
// Also zeroes the stat accumulators (stream-ordered before edge_stats).
// ============================================================================
__global__ void node_prep(const float* __restrict__ x,
                          const float* __restrict__ W1,
                          const float* __restrict__ W2,
                          const float* __restrict__ b0,
                          const float* __restrict__ b1,
                          const float* __restrict__ b2) {
    __shared__ float W1t[256], W2t[256], bt[16];
    int tid = threadIdx.x;
    {
        int j = tid >> 4, k = tid & 15;          // W[j][k] at flat idx tid
        W1t[k * 16 + j] = W1[tid];               // transpose to [k][j]
        W2t[k * 16 + j] = W2[tid];
    }
    if (tid < 16) bt[tid] = b0[tid] + b1[tid] + b2[tid];
    __syncthreads();

    int n = blockIdx.x * blockDim.x + tid;
    if (n < NNODES) {
        const float4* xv = (const float4*)x + n * 4;
        float4 x0 = xv[0], x1 = xv[1], x2 = xv[2], x3 = xv[3];
        float xr[16] = {x0.x, x0.y, x0.z, x0.w, x1.x, x1.y, x1.z, x1.w,
                        x2.x, x2.y, x2.z, x2.w, x3.x, x3.y, x3.z, x3.w};
        float a1[16], a2[16];
        #pragma unroll
        for (int j = 0; j < 16; j++) { a1[j] = bt[j]; a2[j] = 0.f; }
        #pragma unroll
        for (int k = 0; k < 16; k++) {
            float xk = xr[k];
            #pragma unroll
            for (int j = 0; j < 16; j++) {
                a1[j] = fmaf(xk, W1t[k * 16 + j], a1[j]);
                a2[j] = fmaf(xk, W2t[k * 16 + j], a2[j]);
            }
        }
        float4* o1 = (float4*)g_g1 + n * 4;
        float4* o2 = (float4*)g_g2 + n * 4;
        o1[0] = make_float4(a1[0], a1[1], a1[2], a1[3]);
        o1[1] = make_float4(a1[4], a1[5], a1[6], a1[7]);
        o1[2] = make_float4(a1[8], a1[9], a1[10], a1[11]);
        o1[3] = make_float4(a1[12], a1[13], a1[14], a1[15]);
        o2[0] = make_float4(a2[0], a2[1], a2[2], a2[3]);
        o2[1] = make_float4(a2[4], a2[5], a2[6], a2[7]);
        o2[2] = make_float4(a2[8], a2[9], a2[10], a2[11]);
        o2[3] = make_float4(a2[12], a2[13], a2[14], a2[15]);
    }
    if (blockIdx.x == 0 && tid < 32) g_accum[tid] = 0.f;
}

// ============================================================================
// Kernel 2: pass 1 — quad layout (thread q owns features 4q..4q+3).
// W0 rows for this thread's features live in registers (no LDS in the loop).
// Computes e, stores fp16 e to scratch, accumulates fp32 sum/sumsq.
// ============================================================================
__global__ void __launch_bounds__(256) edge_stats(const float* __restrict__ ea,
                                                  const int* __restrict__ ei,
                                                  const float* __restrict__ W0) {
    __shared__ float red[8][32];
    int tid = threadIdx.x;
    int q = tid & 3;
    int lane = tid & 31;

    // w[i][g] = W0[4q+i][4g..4g+3]  (loop-invariant, register-resident)
    float4 w[4][4];
    #pragma unroll
    for (int i = 0; i < 4; i++)
        #pragma unroll
        for (int g = 0; g < 4; g++)
            w[i][g] = ((const float4*)W0)[(4 * q + i) * 4 + g];

    int qid0 = (blockIdx.x * blockDim.x + tid) >> 2;
    int qstride = (gridDim.x * blockDim.x) >> 2;

    float S[4] = {0.f, 0.f, 0.f, 0.f};
    float Q[4] = {0.f, 0.f, 0.f, 0.f};
    const float4* eav = (const float4*)ea;
    const float4* g1v = (const float4*)g_g1;
    const float4* g2v = (const float4*)g_g2;
    h4* ev = (h4*)g_e;

    for (int e = qid0; e < NEDGES; e += qstride) {
        int s = ei[e];
        int d = ei[NEDGES + e];
        float4 av = eav[e * 4 + q];             // lane-consecutive, coalesced
        float4 ga = g1v[s * 4 + q];             // quad covers the 64B record
        float4 gb = g2v[d * 4 + q];
        float acc[4] = {ga.x + gb.x, ga.y + gb.y, ga.z + gb.z, ga.w + gb.w};

        int qbase = lane & 28;
        #pragma unroll
        for (int g = 0; g < 4; g++) {
            int src = qbase | g;
            float x0 = __shfl_sync(0xffffffffu, av.x, src);
            float x1 = __shfl_sync(0xffffffffu, av.y, src);
            float x2 = __shfl_sync(0xffffffffu, av.z, src);
            float x3 = __shfl_sync(0xffffffffu, av.w, src);
            #pragma unroll
            for (int i = 0; i < 4; i++) {
                acc[i] = fmaf(x0, w[i][g].x, acc[i]);
                acc[i] = fmaf(x1, w[i][g].y, acc[i]);
                acc[i] = fmaf(x2, w[i][g].z, acc[i]);
                acc[i] = fmaf(x3, w[i][g].w, acc[i]);
            }
        }

        // fp32 stats (pre-rounding)
        #pragma unroll
        for (int i = 0; i < 4; i++) {
            S[i] += acc[i];
            Q[i] = fmaf(acc[i], acc[i], Q[i]);
        }
        // fp16 e to scratch (8 B per thread, lane-consecutive)
        h4 hv;
        hv.a = __floats2half2_rn(acc[0], acc[1]);
        hv.b = __floats2half2_rn(acc[2], acc[3]);
        ev[e * 4 + q] = hv;
    }

    // Reduce across lanes with same q (offsets 4,8,16): lanes 0..3 hold totals
    #pragma unroll
    for (int i = 0; i < 4; i++) {
        #pragma unroll
        for (int o = 4; o < 32; o <<= 1) {
            S[i] += __shfl_xor_sync(0xffffffffu, S[i], o);
            Q[i] += __shfl_xor_sync(0xffffffffu, Q[i], o);
        }
    }
    int wrp = tid >> 5;
    if (lane < 4) {
        #pragma unroll
        for (int i = 0; i < 4; i++) {
            red[wrp][lane * 4 + i] = S[i];       // feature j = 4*lane + i
            red[wrp][16 + lane * 4 + i] = Q[i];
        }
    }
    __syncthreads();
    if (tid < 32) {
        float acc = 0.f;
        #pragma unroll
        for (int w2 = 0; w2 < 8; w2++) acc += red[w2][tid];
        atomicAdd(&g_accum[tid], acc);
    }
}

// ============================================================================
// Kernel 3: finalize BN affine
// ============================================================================
__global__ void bn_finalize(const float* __restrict__ gamma,
                            const float* __restrict__ beta) {
    int j = threadIdx.x;
    if (j < 16) {
        float inv_n = 1.0f / (float)NEDGES;
        float mean = g_accum[j] * inv_n;
        float var = g_accum[16 + j] * inv_n - mean * mean;
        float sc = gamma[j] * rsqrtf(var + 1e-5f);
        g_scale[j] = sc;
        g_shift[j] = beta[j] - mean * sc;
    }
}

// ============================================================================
// Kernel 4: pass 2 — pure streaming: out = ea + relu(e*scale + shift).
// One float4 (= one (edge, quarter) slice) per thread. No gathers, no matmul.
// ============================================================================
__global__ void __launch_bounds__(256) edge_apply(const float* __restrict__ ea,
                                                  float* __restrict__ out) {
    int idx = blockIdx.x * blockDim.x + threadIdx.x;   // 0 .. NEDGES*4-1
    int q = idx & 3;
    float4 sc = ((const float4*)g_scale)[q];           // broadcast, L1-hit
    float4 sh = ((const float4*)g_shift)[q];

    float4 av = ((const float4*)ea)[idx];
    h4 v = ((const h4*)g_e)[idx];
    float2 f01 = __half22float2(v.a);
    float2 f23 = __half22float2(v.b);

    float4 o;
    o.x = av.x + fmaxf(fmaf(f01.x, sc.x, sh.x), 0.f);
    o.y = av.y + fmaxf(fmaf(f01.y, sc.y, sh.y), 0.f);
    o.z = av.z + fmaxf(fmaf(f23.x, sc.z, sh.z), 0.f);
    o.w = av.w + fmaxf(fmaf(f23.y, sc.w, sh.w), 0.f);
    ((float4*)out)[idx] = o;
}

extern "C" void kernel_launch(void* const* d_in, const int* in_sizes, int n_in,
                              void* d_out, int out_size) {
    (void)in_sizes; (void)n_in; (void)out_size;
    const float* x     = (const float*)d_in[0];
    const int*   ei    = (const int*)d_in[1];     // int32 on device (JAX x64 off)
    const float* ea    = (const float*)d_in[2];
    const float* W0    = (const float*)d_in[3];
    const float* b0    = (const float*)d_in[4];
    const float* W1    = (const float*)d_in[5];
    const float* b1    = (const float*)d_in[6];
    const float* W2    = (const float*)d_in[7];
    const float* b2    = (const float*)d_in[8];
    const float* gamma = (const float*)d_in[9];
    const float* beta  = (const float*)d_in[10];
    float* out = (float*)d_out;

    node_prep<<<(NNODES + 255) / 256, 256>>>(x, W1, W2, b0, b1, b2);
    // qstride = 2500*64 = 160000 divides NEDGES (20 iters), warps stay converged
    edge_stats<<<2500, 256>>>(ea, ei, W0);
    bn_finalize<<<1, 32>>>(gamma, beta);
    edge_apply<<<(NEDGES * 4) / 256, 256>>>(ea, out);   // 50000 blocks, 1 float4/thread
}

// round 11
// speedup vs baseline: 2.2011x; 1.2707x over previous
#include <cuda_runtime.h>
#include <cuda_fp16.h>

#define NEDGES 3200000
#define NNODES 100000

// Scratch (static device allocation; no cudaMalloc anywhere)
static __device__ __align__(256) float g_g1[NNODES * 16];   // x@W1^T + (b0+b1+b2)
static __device__ __align__(256) float g_g2[NNODES * 16];   // x@W2^T
static __device__ __align__(256) __half g_e[NEDGES * 16];   // fp16 pre-BN e (102.4 MB)
static __device__ float g_accum[32];                        // sum[16], sumsq[16]
static __device__ __align__(64) float g_scale[16];
static __device__ __align__(64) float g_shift[16];

struct __align__(8) h4 { __half2 a, b; };                   // 4 halves = 8 B

// ============================================================================
// Kernel 1: per-node precompute g1 = x@W1^T + (b0+b1+b2), g2 = x@W2^T.
// Also zeroes the stat accumulators (stream-ordered before edge_stats).
// ============================================================================
__global__ void node_prep(const float* __restrict__ x,
                          const float* __restrict__ W1,
                          const float* __restrict__ W2,
                          const float* __restrict__ b0,
                          const float* __restrict__ b1,
                          const float* __restrict__ b2) {
    __shared__ float W1t[256], W2t[256], bt[16];
    int tid = threadIdx.x;
    {
        int j = tid >> 4, k = tid & 15;          // W[j][k] at flat idx tid
        W1t[k * 16 + j] = W1[tid];               // transpose to [k][j]
        W2t[k * 16 + j] = W2[tid];
    }
    if (tid < 16) bt[tid] = b0[tid] + b1[tid] + b2[tid];
    __syncthreads();

    int n = blockIdx.x * blockDim.x + tid;
    if (n < NNODES) {
        const float4* xv = (const float4*)x + n * 4;
        float4 x0 = xv[0], x1 = xv[1], x2 = xv[2], x3 = xv[3];
        float xr[16] = {x0.x, x0.y, x0.z, x0.w, x1.x, x1.y, x1.z, x1.w,
                        x2.x, x2.y, x2.z, x2.w, x3.x, x3.y, x3.z, x3.w};
        float a1[16], a2[16];
        #pragma unroll
        for (int j = 0; j < 16; j++) { a1[j] = bt[j]; a2[j] = 0.f; }
        #pragma unroll
        for (int k = 0; k < 16; k++) {
            float xk = xr[k];
            #pragma unroll
            for (int j = 0; j < 16; j++) {
                a1[j] = fmaf(xk, W1t[k * 16 + j], a1[j]);
                a2[j] = fmaf(xk, W2t[k * 16 + j], a2[j]);
            }
        }
        float4* o1 = (float4*)g_g1 + n * 4;
        float4* o2 = (float4*)g_g2 + n * 4;
        o1[0] = make_float4(a1[0], a1[1], a1[2], a1[3]);
        o1[1] = make_float4(a1[4], a1[5], a1[6], a1[7]);
        o1[2] = make_float4(a1[8], a1[9], a1[10], a1[11]);
        o1[3] = make_float4(a1[12], a1[13], a1[14], a1[15]);
        o2[0] = make_float4(a2[0], a2[1], a2[2], a2[3]);
        o2[1] = make_float4(a2[4], a2[5], a2[6], a2[7]);
        o2[2] = make_float4(a2[8], a2[9], a2[10], a2[11]);
        o2[3] = make_float4(a2[12], a2[13], a2[14], a2[15]);
    }
    if (blockIdx.x == 0 && tid < 32) g_accum[tid] = 0.f;
}

// ============================================================================
// Kernel 2: pass 1 — quad layout (thread q owns features 4q..4q+3).
// W0 rows register-resident; one-iteration-ahead software pipeline so every
// global load (indices, ea slice, both node gathers) has a full loop body of
// latency cover. Gathers are consumed at the END of the FMA chain.
// __launch_bounds__(256,2): 128-reg budget, 16 warps/SM guaranteed.
// ============================================================================
__global__ void __launch_bounds__(256, 2) edge_stats(const float* __restrict__ ea,
                                                     const int* __restrict__ ei,
                                                     const float* __restrict__ W0) {
    __shared__ float red[8][32];
    int tid = threadIdx.x;
    int q = tid & 3;
    int lane = tid & 31;
    int qbase = lane & 28;

    // w[i][g] = W0[4q+i][4g..4g+3]  (loop-invariant, register-resident)
    float4 w[4][4];
    #pragma unroll
    for (int i = 0; i < 4; i++)
        #pragma unroll
        for (int g = 0; g < 4; g++)
            w[i][g] = __ldg(&((const float4*)W0)[(4 * q + i) * 4 + g]);

    int qid0 = (blockIdx.x * blockDim.x + tid) >> 2;
    int qstride = (gridDim.x * blockDim.x) >> 2;

    float S[4] = {0.f, 0.f, 0.f, 0.f};
    float Q[4] = {0.f, 0.f, 0.f, 0.f};
    const float4* eav = (const float4*)ea;
    const float4* g1v = (const float4*)g_g1;
    const float4* g2v = (const float4*)g_g2;
    h4* ev = (h4*)g_e;

    // Prologue: loads for first edge
    int e = qid0;
    float4 av, ga, gb;
    {
        int s = ei[e];
        int d = ei[NEDGES + e];
        av = eav[e * 4 + q];
        ga = g1v[s * 4 + q];
        gb = g2v[d * 4 + q];
    }

    while (e < NEDGES) {
        // ---- prefetch next iteration (predicated off on the last one) ----
        int en = e + qstride;
        float4 avn, gan, gbn;
        if (en < NEDGES) {
            int sn = ei[en];
            int dn = ei[NEDGES + en];
            avn = eav[en * 4 + q];
            gan = g1v[sn * 4 + q];
            gbn = g2v[dn * 4 + q];
        }

        // ---- matmul quarter: acc = (ea @ W0^T)[4q..4q+3], gathers added last
        float acc[4] = {0.f, 0.f, 0.f, 0.f};
        #pragma unroll
        for (int g = 0; g < 4; g++) {
            int src = qbase | g;
            float x0 = __shfl_sync(0xffffffffu, av.x, src);
            float x1 = __shfl_sync(0xffffffffu, av.y, src);
            float x2 = __shfl_sync(0xffffffffu, av.z, src);
            float x3 = __shfl_sync(0xffffffffu, av.w, src);
            #pragma unroll
            for (int i = 0; i < 4; i++) {
                acc[i] = fmaf(x0, w[i][g].x, acc[i]);
                acc[i] = fmaf(x1, w[i][g].y, acc[i]);
                acc[i] = fmaf(x2, w[i][g].z, acc[i]);
                acc[i] = fmaf(x3, w[i][g].w, acc[i]);
            }
        }
        acc[0] += ga.x + gb.x;
        acc[1] += ga.y + gb.y;
        acc[2] += ga.z + gb.z;
        acc[3] += ga.w + gb.w;

        // fp32 stats (pre-rounding)
        #pragma unroll
        for (int i = 0; i < 4; i++) {
            S[i] += acc[i];
            Q[i] = fmaf(acc[i], acc[i], Q[i]);
        }
        // fp16 e to scratch (8 B per thread, lane-consecutive)
        h4 hv;
        hv.a = __floats2half2_rn(acc[0], acc[1]);
        hv.b = __floats2half2_rn(acc[2], acc[3]);
        ev[e * 4 + q] = hv;

        // rotate pipeline
        e = en; av = avn; ga = gan; gb = gbn;
    }

    // Reduce across lanes with same q (offsets 4,8,16): lanes 0..3 hold totals
    #pragma unroll
    for (int i = 0; i < 4; i++) {
        #pragma unroll
        for (int o = 4; o < 32; o <<= 1) {
            S[i] += __shfl_xor_sync(0xffffffffu, S[i], o);
            Q[i] += __shfl_xor_sync(0xffffffffu, Q[i], o);
        }
    }
    int wrp = tid >> 5;
    if (lane < 4) {
        #pragma unroll
        for (int i = 0; i < 4; i++) {
            red[wrp][lane * 4 + i] = S[i];       // feature j = 4*lane + i
            red[wrp][16 + lane * 4 + i] = Q[i];
        }
    }
    __syncthreads();
    if (tid < 32) {
        float acc = 0.f;
        #pragma unroll
        for (int w2 = 0; w2 < 8; w2++) acc += red[w2][tid];
        atomicAdd(&g_accum[tid], acc);
    }
}

// ============================================================================
// Kernel 3: finalize BN affine
// ============================================================================
__global__ void bn_finalize(const float* __restrict__ gamma,
                            const float* __restrict__ beta) {
    int j = threadIdx.x;
    if (j < 16) {
        float inv_n = 1.0f / (float)NEDGES;
        float mean = g_accum[j] * inv_n;
        float var = g_accum[16 + j] * inv_n - mean * mean;
        float sc = gamma[j] * rsqrtf(var + 1e-5f);
        g_scale[j] = sc;
        g_shift[j] = beta[j] - mean * sc;
    }
}

// ============================================================================
// Kernel 4: pass 2 — pure streaming: out = ea + relu(e*scale + shift).
// One float4 (= one (edge, quarter) slice) per thread. At DRAM roofline.
// ============================================================================
__global__ void __launch_bounds__(256) edge_apply(const float* __restrict__ ea,
                                                  float* __restrict__ out) {
    int idx = blockIdx.x * blockDim.x + threadIdx.x;   // 0 .. NEDGES*4-1
    int q = idx & 3;
    float4 sc = ((const float4*)g_scale)[q];           // broadcast, L1-hit
    float4 sh = ((const float4*)g_shift)[q];

    float4 av = ((const float4*)ea)[idx];
    h4 v = ((const h4*)g_e)[idx];
    float2 f01 = __half22float2(v.a);
    float2 f23 = __half22float2(v.b);

    float4 o;
    o.x = av.x + fmaxf(fmaf(f01.x, sc.x, sh.x), 0.f);
    o.y = av.y + fmaxf(fmaf(f01.y, sc.y, sh.y), 0.f);
    o.z = av.z + fmaxf(fmaf(f23.x, sc.z, sh.z), 0.f);
    o.w = av.w + fmaxf(fmaf(f23.y, sc.w, sh.w), 0.f);
    ((float4*)out)[idx] = o;
}

extern "C" void kernel_launch(void* const* d_in, const int* in_sizes, int n_in,
                              void* d_out, int out_size) {
    (void)in_sizes; (void)n_in; (void)out_size;
    const float* x     = (const float*)d_in[0];
    const int*   ei    = (const int*)d_in[1];     // int32 on device (JAX x64 off)
    const float* ea    = (const float*)d_in[2];
    const float* W0    = (const float*)d_in[3];
    const float* b0    = (const float*)d_in[4];
    const float* W1    = (const float*)d_in[5];
    const float* b1    = (const float*)d_in[6];
    const float* W2    = (const float*)d_in[7];
    const float* b2    = (const float*)d_in[8];
    const float* gamma = (const float*)d_in[9];
    const float* beta  = (const float*)d_in[10];
    float* out = (float*)d_out;

    node_prep<<<(NNODES + 255) / 256, 256>>>(x, W1, W2, b0, b1, b2);
    // qstride = 2000*64 = 128000 divides NEDGES (25 iters), warps stay converged
    edge_stats<<<2000, 256>>>(ea, ei, W0);
    bn_finalize<<<1, 32>>>(gamma, beta);
    edge_apply<<<(NEDGES * 4) / 256, 256>>>(ea, out);   // 50000 blocks, 1 float4/thread
}

// round 12
// speedup vs baseline: 2.3988x; 1.0898x over previous
#include <cuda_runtime.h>
#include <cuda_fp16.h>

#define NEDGES 3200000
#define NNODES 100000

// edge_stats launch geometry (compile-time so the loop is counted/predicate-free)
#define ES_BLOCKS 2000
#define ES_THREADS 256
#define QSTRIDE ((ES_BLOCKS * ES_THREADS) / 4)   // 128000 quads
#define ES_ITERS (NEDGES / QSTRIDE)              // 25 exact

// Scratch (static device allocation; no cudaMalloc anywhere)
static __device__ __align__(256) float g_g1[NNODES * 16];   // x@W1^T + (b0+b1+b2)
static __device__ __align__(256) float g_g2[NNODES * 16];   // x@W2^T
static __device__ __align__(256) __half g_e[NEDGES * 16];   // fp16 pre-BN e (102.4 MB)
static __device__ float g_accum[32];                        // sum[16], sumsq[16]
static __device__ __align__(64) float g_scale[16];
static __device__ __align__(64) float g_shift[16];

struct __align__(8) h4 { __half2 a, b; };                   // 4 halves = 8 B

// ============================================================================
// Kernel 1: per-node precompute g1 = x@W1^T + (b0+b1+b2), g2 = x@W2^T.
// Also zeroes the stat accumulators (stream-ordered before edge_stats).
// ============================================================================
__global__ void node_prep(const float* __restrict__ x,
                          const float* __restrict__ W1,
                          const float* __restrict__ W2,
                          const float* __restrict__ b0,
                          const float* __restrict__ b1,
                          const float* __restrict__ b2) {
    __shared__ float W1t[256], W2t[256], bt[16];
    int tid = threadIdx.x;
    {
        int j = tid >> 4, k = tid & 15;          // W[j][k] at flat idx tid
        W1t[k * 16 + j] = W1[tid];               // transpose to [k][j]
        W2t[k * 16 + j] = W2[tid];
    }
    if (tid < 16) bt[tid] = b0[tid] + b1[tid] + b2[tid];
    __syncthreads();

    int n = blockIdx.x * blockDim.x + tid;
    if (n < NNODES) {
        const float4* xv = (const float4*)x + n * 4;
        float4 x0 = xv[0], x1 = xv[1], x2 = xv[2], x3 = xv[3];
        float xr[16] = {x0.x, x0.y, x0.z, x0.w, x1.x, x1.y, x1.z, x1.w,
                        x2.x, x2.y, x2.z, x2.w, x3.x, x3.y, x3.z, x3.w};
        float a1[16], a2[16];
        #pragma unroll
        for (int j = 0; j < 16; j++) { a1[j] = bt[j]; a2[j] = 0.f; }
        #pragma unroll
        for (int k = 0; k < 16; k++) {
            float xk = xr[k];
            #pragma unroll
            for (int j = 0; j < 16; j++) {
                a1[j] = fmaf(xk, W1t[k * 16 + j], a1[j]);
                a2[j] = fmaf(xk, W2t[k * 16 + j], a2[j]);
            }
        }
        float4* o1 = (float4*)g_g1 + n * 4;
        float4* o2 = (float4*)g_g2 + n * 4;
        o1[0] = make_float4(a1[0], a1[1], a1[2], a1[3]);
        o1[1] = make_float4(a1[4], a1[5], a1[6], a1[7]);
        o1[2] = make_float4(a1[8], a1[9], a1[10], a1[11]);
        o1[3] = make_float4(a1[12], a1[13], a1[14], a1[15]);
        o2[0] = make_float4(a2[0], a2[1], a2[2], a2[3]);
        o2[1] = make_float4(a2[4], a2[5], a2[6], a2[7]);
        o2[2] = make_float4(a2[8], a2[9], a2[10], a2[11]);
        o2[3] = make_float4(a2[12], a2[13], a2[14], a2[15]);
    }
    if (blockIdx.x == 0 && tid < 32) g_accum[tid] = 0.f;
}

// ============================================================================
// Kernel 2: pass 1 — quad layout (thread q owns features 4q..4q+3).
// 3-stage software pipeline: index loads 2 iterations ahead, data loads
// (ea slice + both node gathers) 1 iteration ahead, compute current.
// Counted loop (25 iters exactly), no bounds predicates in steady state.
// W0 rows register-resident. __launch_bounds__(256,2) = 128-reg budget.
// ============================================================================
__global__ void __launch_bounds__(ES_THREADS, 2) edge_stats(const float* __restrict__ ea,
                                                            const int* __restrict__ ei,
                                                            const float* __restrict__ W0) {
    __shared__ float red[8][32];
    int tid = threadIdx.x;
    int q = tid & 3;
    int lane = tid & 31;
    int qbase = lane & 28;

    // w[i][g] = W0[4q+i][4g..4g+3]  (loop-invariant, register-resident)
    float4 w[4][4];
    #pragma unroll
    for (int i = 0; i < 4; i++)
        #pragma unroll
        for (int g = 0; g < 4; g++)
            w[i][g] = __ldg(&((const float4*)W0)[(4 * q + i) * 4 + g]);

    int qid0 = (blockIdx.x * blockDim.x + tid) >> 2;

    float S[4] = {0.f, 0.f, 0.f, 0.f};
    float Q[4] = {0.f, 0.f, 0.f, 0.f};
    const float4* eav = (const float4*)ea;
    const float4* g1v = (const float4*)g_g1;
    const float4* g2v = (const float4*)g_g2;
    float2* ev = (float2*)g_e;

    // ---- pipeline prologue ----
    int e0 = qid0;
    int e1 = e0 + QSTRIDE;
    int s0 = ei[e0], d0 = ei[NEDGES + e0];       // idx iter0
    int s1 = ei[e1], d1 = ei[NEDGES + e1];       // idx iter1
    float4 av0 = __ldcs(&eav[e0 * 4 + q]);       // data iter0 (streaming)
    float4 ga0 = g1v[s0 * 4 + q];
    float4 gb0 = g2v[d0 * 4 + q];

    #pragma unroll 1
    for (int it = 0; it < ES_ITERS; it++) {
        // stage B: data loads for iter+1 (indices arrived a full body ago)
        float4 av1, ga1, gb1;
        if (it + 1 < ES_ITERS) {
            av1 = __ldcs(&eav[e1 * 4 + q]);
            ga1 = g1v[s1 * 4 + q];
            gb1 = g2v[d1 * 4 + q];
        }
        // stage A: index loads for iter+2
        int e2 = e1 + QSTRIDE, s2 = 0, d2 = 0;
        if (it + 2 < ES_ITERS) {
            s2 = ei[e2];
            d2 = ei[NEDGES + e2];
        }

        // stage C: compute current edge. acc = (ea@W0^T) quarter; gathers last.
        float acc[4] = {0.f, 0.f, 0.f, 0.f};
        #pragma unroll
        for (int g = 0; g < 4; g++) {
            int src = qbase | g;
            float x0 = __shfl_sync(0xffffffffu, av0.x, src);
            float x1 = __shfl_sync(0xffffffffu, av0.y, src);
            float x2 = __shfl_sync(0xffffffffu, av0.z, src);
            float x3 = __shfl_sync(0xffffffffu, av0.w, src);
            #pragma unroll
            for (int i = 0; i < 4; i++) {
                acc[i] = fmaf(x0, w[i][g].x, acc[i]);
                acc[i] = fmaf(x1, w[i][g].y, acc[i]);
                acc[i] = fmaf(x2, w[i][g].z, acc[i]);
                acc[i] = fmaf(x3, w[i][g].w, acc[i]);
            }
        }
        acc[0] += ga0.x + gb0.x;
        acc[1] += ga0.y + gb0.y;
        acc[2] += ga0.z + gb0.z;
        acc[3] += ga0.w + gb0.w;

        // fp32 stats (pre-rounding)
        #pragma unroll
        for (int i = 0; i < 4; i++) {
            S[i] += acc[i];
            Q[i] = fmaf(acc[i], acc[i], Q[i]);
        }
        // fp16 e to scratch (8 B/thread, lane-consecutive, streaming store)
        union { h4 h; float2 f; } hv;
        hv.h.a = __floats2half2_rn(acc[0], acc[1]);
        hv.h.b = __floats2half2_rn(acc[2], acc[3]);
        __stcs(&ev[e0 * 4 + q], hv.f);

        // rotate pipeline
        e0 = e1; av0 = av1; ga0 = ga1; gb0 = gb1;
        e1 = e2; s1 = s2; d1 = d2;
    }

    // Reduce across lanes with same q (offsets 4,8,16): lanes 0..3 hold totals
    #pragma unroll
    for (int i = 0; i < 4; i++) {
        #pragma unroll
        for (int o = 4; o < 32; o <<= 1) {
            S[i] += __shfl_xor_sync(0xffffffffu, S[i], o);
            Q[i] += __shfl_xor_sync(0xffffffffu, Q[i], o);
        }
    }
    int wrp = tid >> 5;
    if (lane < 4) {
        #pragma unroll
        for (int i = 0; i < 4; i++) {
            red[wrp][lane * 4 + i] = S[i];       // feature j = 4*lane + i
            red[wrp][16 + lane * 4 + i] = Q[i];
        }
    }
    __syncthreads();
    if (tid < 32) {
        float acc = 0.f;
        #pragma unroll
        for (int w2 = 0; w2 < 8; w2++) acc += red[w2][tid];
        atomicAdd(&g_accum[tid], acc);
    }
}

// ============================================================================
// Kernel 3: finalize BN affine
// ============================================================================
__global__ void bn_finalize(const float* __restrict__ gamma,
                            const float* __restrict__ beta) {
    int j = threadIdx.x;
    if (j < 16) {
        float inv_n = 1.0f / (float)NEDGES;
        float mean = g_accum[j] * inv_n;
        float var = g_accum[16 + j] * inv_n - mean * mean;
        float sc = gamma[j] * rsqrtf(var + 1e-5f);
        g_scale[j] = sc;
        g_shift[j] = beta[j] - mean * sc;
    }
}

// ============================================================================
// Kernel 4: pass 2 — pure streaming: out = ea + relu(e*scale + shift).
// One float4 (= one (edge, quarter) slice) per thread. At DRAM roofline.
// ============================================================================
__global__ void __launch_bounds__(256) edge_apply(const float* __restrict__ ea,
                                                  float* __restrict__ out) {
    int idx = blockIdx.x * blockDim.x + threadIdx.x;   // 0 .. NEDGES*4-1
    int q = idx & 3;
    float4 sc = ((const float4*)g_scale)[q];           // broadcast, L1-hit
    float4 sh = ((const float4*)g_shift)[q];

    float4 av = ((const float4*)ea)[idx];
    h4 v = ((const h4*)g_e)[idx];
    float2 f01 = __half22float2(v.a);
    float2 f23 = __half22float2(v.b);

    float4 o;
    o.x = av.x + fmaxf(fmaf(f01.x, sc.x, sh.x), 0.f);
    o.y = av.y + fmaxf(fmaf(f01.y, sc.y, sh.y), 0.f);
    o.z = av.z + fmaxf(fmaf(f23.x, sc.z, sh.z), 0.f);
    o.w = av.w + fmaxf(fmaf(f23.y, sc.w, sh.w), 0.f);
    ((float4*)out)[idx] = o;
}

extern "C" void kernel_launch(void* const* d_in, const int* in_sizes, int n_in,
                              void* d_out, int out_size) {
    (void)in_sizes; (void)n_in; (void)out_size;
    const float* x     = (const float*)d_in[0];
    const int*   ei    = (const int*)d_in[1];     // int32 on device (JAX x64 off)
    const float* ea    = (const float*)d_in[2];
    const float* W0    = (const float*)d_in[3];
    const float* b0    = (const float*)d_in[4];
    const float* W1    = (const float*)d_in[5];
    const float* b1    = (const float*)d_in[6];
    const float* W2    = (const float*)d_in[7];
    const float* b2    = (const float*)d_in[8];
    const float* gamma = (const float*)d_in[9];
    const float* beta  = (const float*)d_in[10];
    float* out = (float*)d_out;

    node_prep<<<(NNODES + 255) / 256, 256>>>(x, W1, W2, b0, b1, b2);
    edge_stats<<<ES_BLOCKS, ES_THREADS>>>(ea, ei, W0);  // 25 exact iters/thread
    bn_finalize<<<1, 32>>>(gamma, beta);
    edge_apply<<<(NEDGES * 4) / 256, 256>>>(ea, out);   // 50000 blocks, 1 float4/thread
}